// round 16
// baseline (speedup 1.0000x reference)
#include <cuda_runtime.h>
#include <math.h>
#include <stdint.h>

// ============================================================================
// Sinkhorn divergence, N=M=8192, D=64.
// Round 8: strip kernel with per-PAIR barriers.
//  - 128-aligned symmetric chunks (tail path deleted; below-diag cols masked
//    via +INF cost, store predicate keeps coverage exact)
//  - one __syncthreads per 256 cols; merge spread over all 256 threads
//  - register double-buffer prefetch retained; EX2 inline PTX; skip votes
// ============================================================================

#define NMAX  8192
#define DDIM  64
#define LOG2E 1.4426950408889634f
#define LN2   0.6931471805599453f
#define PW    136   // partial slots: 128 col-bands + 8 row-chunks

static __device__ float d_Cxy[(size_t)NMAX * NMAX];
static __device__ float d_Cxx[(size_t)NMAX * NMAX];   // upper tiles only
static __device__ float d_Cyy[(size_t)NMAX * NMAX];   // upper tiles only
static __device__ float d_sq[2][NMAX];
static __device__ float d_vec[12][NMAX];
static __device__ float2 d_P[3][(size_t)PW * NMAX];

__device__ __forceinline__ float ex2f(float x) {
    float y;
    asm("ex2.approx.ftz.f32 %0, %1;" : "=f"(y) : "f"(x));
    return y;
}
__device__ __forceinline__ float lg2f(float x) {
    float y;
    asm("lg2.approx.ftz.f32 %0, %1;" : "=f"(y) : "f"(x));
    return y;
}

// ---------------------------------------------------------------------------
__global__ void sqnorm_kernel(const float* __restrict__ X, float* __restrict__ out,
                              int n, int d) {
    int row = blockIdx.x * (blockDim.x >> 5) + (threadIdx.x >> 5);
    int lane = threadIdx.x & 31;
    if (row >= n) return;
    float s = 0.f;
    for (int c = lane; c < d; c += 32) {
        float v = X[(size_t)row * d + c];
        s += v * v;
    }
#pragma unroll
    for (int o = 16; o; o >>= 1) s += __shfl_xor_sync(0xFFFFFFFFu, s, o);
    if (lane == 0) out[row] = s;
}

// ---------------------------------------------------------------------------
#define BM 128
#define BKC 32

__global__ __launch_bounds__(256) void cost_gemm_kernel(
    const float* __restrict__ A, const float* __restrict__ B,
    const float* __restrict__ sqa, const float* __restrict__ sqb,
    float* __restrict__ C1, int nB, int d, int sym)
{
    int bj = blockIdx.x, bi = blockIdx.y;
    if (sym && bi > bj) return;

    __shared__ float As[BKC][BM + 4];
    __shared__ float Bs[BKC][BM + 4];

    int tid = threadIdx.x;
    int ti = tid & 15, tj = tid >> 4;
    int i0 = ti * 8, j0 = tj * 8;

    const float* Ab = A + (size_t)bi * BM * d;
    const float* Bb = B + (size_t)bj * BM * d;

    float acc[8][8];
#pragma unroll
    for (int a = 0; a < 8; a++)
#pragma unroll
        for (int b = 0; b < 8; b++) acc[a][b] = 0.f;

    for (int kk = 0; kk < d; kk += BKC) {
#pragma unroll
        for (int v = tid; v < 1024; v += 256) {
            int r = v >> 3, c4 = (v & 7) * 4;
            float4 a = *(const float4*)(Ab + (size_t)r * d + kk + c4);
            As[c4 + 0][r] = a.x; As[c4 + 1][r] = a.y;
            As[c4 + 2][r] = a.z; As[c4 + 3][r] = a.w;
            float4 b = *(const float4*)(Bb + (size_t)r * d + kk + c4);
            Bs[c4 + 0][r] = b.x; Bs[c4 + 1][r] = b.y;
            Bs[c4 + 2][r] = b.z; Bs[c4 + 3][r] = b.w;
        }
        __syncthreads();
#pragma unroll
        for (int k = 0; k < BKC; k++) {
            float4 a0 = *(const float4*)&As[k][i0];
            float4 a1 = *(const float4*)&As[k][i0 + 4];
            float4 b0 = *(const float4*)&Bs[k][j0];
            float4 b1 = *(const float4*)&Bs[k][j0 + 4];
            float av[8] = {a0.x, a0.y, a0.z, a0.w, a1.x, a1.y, a1.z, a1.w};
            float bv[8] = {b0.x, b0.y, b0.z, b0.w, b1.x, b1.y, b1.z, b1.w};
#pragma unroll
            for (int ii = 0; ii < 8; ii++)
#pragma unroll
                for (int jj = 0; jj < 8; jj++)
                    acc[ii][jj] += av[ii] * bv[jj];
        }
        __syncthreads();
    }

    float si[8], sj[8];
#pragma unroll
    for (int ii = 0; ii < 8; ii++) si[ii] = 0.5f * sqa[bi * BM + i0 + ii];
#pragma unroll
    for (int jj = 0; jj < 8; jj++) sj[jj] = 0.5f * sqb[bj * BM + j0 + jj];

#pragma unroll
    for (int ii = 0; ii < 8; ii++) {
        size_t off = (size_t)(bi * BM + i0 + ii) * nB + bj * BM + j0;
        float4 w0 = make_float4(
            fmaxf(si[ii] + sj[0] - acc[ii][0], 0.f),
            fmaxf(si[ii] + sj[1] - acc[ii][1], 0.f),
            fmaxf(si[ii] + sj[2] - acc[ii][2], 0.f),
            fmaxf(si[ii] + sj[3] - acc[ii][3], 0.f));
        float4 w1 = make_float4(
            fmaxf(si[ii] + sj[4] - acc[ii][4], 0.f),
            fmaxf(si[ii] + sj[5] - acc[ii][5], 0.f),
            fmaxf(si[ii] + sj[6] - acc[ii][6], 0.f),
            fmaxf(si[ii] + sj[7] - acc[ii][7], 0.f));
        *(float4*)(C1 + off) = w0;
        *(float4*)(C1 + off + 4) = w1;
    }
}

// ---------------------------------------------------------------------------
// strip kernel: 64-row x (<=1024)-col chunks, all cols 128-panel aligned.
// ---------------------------------------------------------------------------
struct StripP {
    const float* C[3];
    float2*      P[3];
    const float* potr[3];
    const float* potc[3];
    float        lwr[3], lwc[3];
    const float* eps_list;
    int eps_idx;
    int nn, nbands, cpr, blocksXY, blocksSym;
};

__global__ __launch_bounds__(256, 2) void strip_kernel(StripP prm)
{
    int nn = prm.nn;
    int id = blockIdx.x;
    int mat, band, chunk;
    if (id < prm.blocksXY) {
        mat = 0;
        band = id / prm.cpr;
        chunk = id - band * prm.cpr;
    } else {
        id -= prm.blocksXY;
        mat = 1 + id / prm.blocksSym;
        int sid = id - (mat - 1) * prm.blocksSym;
        int b = 0;
        for (;;) {
            int nc = (prm.nbands - b + 15) >> 4;
            if (sid < nc) break;
            sid -= nc; b++;
        }
        band = b; chunk = sid;
    }
    int c0, c1;
    if (mat == 0) { c0 = chunk << 10; c1 = c0 + 1024; }
    else {
        c0 = ((band << 6) & ~127) + (chunk << 10);   // 128-aligned start
        c1 = min(c0 + 1024, nn);
    }
    int row0 = band << 6;

    const float* __restrict__ C = prm.C[mat];
    float2* __restrict__ P = prm.P[mat];
    const float* potr = prm.potr[mat];
    const float* potc = prm.potc[mat];

    float eps = prm.eps_list[prm.eps_idx];
    float ie2 = LOG2E / eps;
    float lwr2 = prm.lwr[mat] * LOG2E;
    float lwc2 = prm.lwc[mat] * LOG2E;

    int w = threadIdx.x >> 5, l = threadIdx.x & 31;
    int rbase = row0 + w * 8;

    float har[8];
#pragma unroll
    for (int r = 0; r < 8; r++)
        har[r] = potr ? fmaf(potr[rbase + r], ie2, lwr2) : lwr2;

    float rmx[8], rs[8];
#pragma unroll
    for (int r = 0; r < 8; r++) { rmx[r] = -3.4e38f; rs[r] = 0.f; }

    __shared__ float2 smc[2][8][256];
    const float* Cb = C + (size_t)rbase * nn;

#define LOADP(U, H, PP) do {                                                   \
        int _j = (PP) + l * 4;                                                 \
        _Pragma("unroll")                                                      \
        for (int _r = 0; _r < 8; _r++)                                         \
            U[_r] = *(const float4*)(Cb + (size_t)_r * nn + _j);               \
        if (potc) {                                                            \
            float4 _p = *(const float4*)(potc + _j);                           \
            H.x = fmaf(_p.x, ie2, lwc2); H.y = fmaf(_p.y, ie2, lwc2);          \
            H.z = fmaf(_p.z, ie2, lwc2); H.w = fmaf(_p.w, ie2, lwc2);          \
        } else H = make_float4(lwc2, lwc2, lwc2, lwc2);                        \
    } while (0)

#define COMPUTE(U, H, PAR, SLOT) do {                                          \
        float cm0 = -3.0e38f, cm1 = -3.0e38f, cm2 = -3.0e38f, cm3 = -3.0e38f;  \
        _Pragma("unroll")                                                      \
        for (int r = 0; r < 8; r++) {                                          \
            U[r].x *= -ie2; U[r].y *= -ie2; U[r].z *= -ie2; U[r].w *= -ie2;    \
            float v0 = U[r].x + H.x, v1 = U[r].y + H.y;                        \
            float v2 = U[r].z + H.z, v3 = U[r].w + H.w;                        \
            float m4 = fmaxf(fmaxf(v0, v1), fmaxf(v2, v3));                    \
            if (__any_sync(0xFFFFFFFFu, m4 > rmx[r] - 24.f)) {                 \
                float mn = fmaxf(rmx[r], m4);                                  \
                float e = ex2f(v0 - mn) + ex2f(v1 - mn)                        \
                        + ex2f(v2 - mn) + ex2f(v3 - mn);                       \
                rs[r] = fmaf(rs[r], ex2f(rmx[r] - mn), e);                     \
                rmx[r] = mn;                                                   \
            }                                                                  \
            float a = har[r];                                                  \
            cm0 = fmaxf(cm0, U[r].x + a); cm1 = fmaxf(cm1, U[r].y + a);        \
            cm2 = fmaxf(cm2, U[r].z + a); cm3 = fmaxf(cm3, U[r].w + a);        \
        }                                                                      \
        float cs0 = 0.f, cs1 = 0.f, cs2 = 0.f, cs3 = 0.f;                      \
        _Pragma("unroll")                                                      \
        for (int r = 0; r < 8; r++) {                                          \
            float t0 = har[r] - cm0, t1 = har[r] - cm1;                        \
            float t2 = har[r] - cm2, t3 = har[r] - cm3;                        \
            float w0 = U[r].x + t0, w1 = U[r].y + t1;                          \
            float w2 = U[r].z + t2, w3 = U[r].w + t3;                          \
            float m4c = fmaxf(fmaxf(w0, w1), fmaxf(w2, w3));                   \
            if (__any_sync(0xFFFFFFFFu, m4c > -24.f)) {                        \
                cs0 += ex2f(w0); cs1 += ex2f(w1);                              \
                cs2 += ex2f(w2); cs3 += ex2f(w3);                              \
            }                                                                  \
        }                                                                      \
        smc[PAR][w][(SLOT) * 128 + l * 4 + 0] = make_float2(cm0, cs0);         \
        smc[PAR][w][(SLOT) * 128 + l * 4 + 1] = make_float2(cm1, cs1);         \
        smc[PAR][w][(SLOT) * 128 + l * 4 + 2] = make_float2(cm2, cs2);         \
        smc[PAR][w][(SLOT) * 128 + l * 4 + 3] = make_float2(cm3, cs3);         \
    } while (0)

#define MERGE(PB, NC, PAR) do {                                                \
        __syncthreads();                                                       \
        if (threadIdx.x < (NC)) {                                              \
            int t = threadIdx.x;                                               \
            float2 a = smc[PAR][0][t];                                         \
            float m = a.x, s = a.y;                                            \
            _Pragma("unroll")                                                  \
            for (int ww = 1; ww < 8; ww++) {                                   \
                float2 b = smc[PAR][ww][t];                                    \
                float mn = fmaxf(m, b.x);                                      \
                s = fmaf(s, ex2f(m - mn), b.y * ex2f(b.x - mn));               \
                m = mn;                                                        \
            }                                                                  \
            int jj = (PB) + t;                                                 \
            if (!(mat && ((jj >> 6) <= band)))                                 \
                P[(size_t)band * nn + jj] = make_float2(m, s);                 \
        }                                                                      \
    } while (0)

    int npan = (c1 - c0) >> 7;
    float4 u[8], un[8], hcur, hn;
    LOADP(u, hcur, c0);
    // mask below-diagonal 64 cols of odd bands' first chunk: +INF cost -> 0
    if (mat && chunk == 0 && (band & 1) && l < 16) {
        float inf = __int_as_float(0x7f800000);
#pragma unroll
        for (int r = 0; r < 8; r++) u[r] = make_float4(inf, inf, inf, inf);
    }
    int par = 0;
    for (int pi = 0; pi < npan; pi++) {
        if (pi + 1 < npan) LOADP(un, hn, c0 + ((pi + 1) << 7));
        COMPUTE(u, hcur, par, pi & 1);
        if (pi & 1) {
            MERGE(c0 + ((pi - 1) << 7), 256, par);
            par ^= 1;
        }
#pragma unroll
        for (int r = 0; r < 8; r++) u[r] = un[r];
        hcur = hn;
    }
    if (npan & 1) MERGE(c0 + ((npan - 1) << 7), 128, par);

    // row partial output (once per chunk)
#pragma unroll
    for (int r = 0; r < 8; r++) {
        float m = rmx[r], s = rs[r];
#pragma unroll
        for (int o = 16; o; o >>= 1) {
            float m2 = __shfl_xor_sync(0xFFFFFFFFu, m, o);
            float s2 = __shfl_xor_sync(0xFFFFFFFFu, s, o);
            float mn = fmaxf(m, m2);
            s = fmaf(s, ex2f(m - mn), s2 * ex2f(m2 - mn));
            m = mn;
        }
        if (l == 0)
            P[(size_t)(prm.nbands + chunk) * nn + rbase + r] = make_float2(m, s);
    }
#undef LOADP
#undef COMPUTE
#undef MERGE
}

// ---------------------------------------------------------------------------
struct S2J {
    const float2* P[4];
    const float*  oldv[4];
    float*        out[4];
    int colLim[4];
    int chLim[4];
};

__global__ __launch_bounds__(256) void stage2_kernel(
    S2J jb, const float* __restrict__ eps_list, int eps_idx, int nn, int nbands)
{
    int job = blockIdx.y;
    int row = blockIdx.x * 256 + threadIdx.x;
    float eps = eps_list[eps_idx];
    const float2* __restrict__ P = jb.P[job];
    int band = row >> 6;
    int cl = jb.colLim[job]; if (cl < 0) cl = band;
    int ch = jb.chLim[job];  if (ch < 0) ch = (nbands - band + 15) >> 4;

    float mx = -3.4e38f, s = 0.f;
    for (int t = 0; t < cl; t++) {
        float2 p = P[(size_t)t * nn + row];
        float mn = fmaxf(mx, p.x);
        s = fmaf(s, ex2f(mx - mn), p.y * ex2f(p.x - mn));
        mx = mn;
    }
    for (int t = 0; t < ch; t++) {
        float2 p = P[(size_t)(nbands + t) * nn + row];
        float mn = fmaxf(mx, p.x);
        s = fmaf(s, ex2f(mx - mn), p.y * ex2f(p.x - mn));
        mx = mn;
    }
    float res = -eps * LN2 * (mx + lg2f(s));
    const float* ov = jb.oldv[job];
    jb.out[job][row] = ov ? 0.5f * (ov[row] + res) : res;
}

// ---------------------------------------------------------------------------
__global__ void final_reduce_kernel(float* __restrict__ out, int n) {
    __shared__ float red[256];
    float s = 0.f;
    for (int i = threadIdx.x; i < n; i += 256)
        s += (d_vec[8][i] - d_vec[10][i]) + (d_vec[9][i] - d_vec[11][i]);
    red[threadIdx.x] = s;
    __syncthreads();
    for (int o = 128; o; o >>= 1) {
        if (threadIdx.x < o) red[threadIdx.x] += red[threadIdx.x + o];
        __syncthreads();
    }
    if (threadIdx.x == 0) out[0] = red[0] / (float)n;
}

// ---------------------------------------------------------------------------
extern "C" void kernel_launch(void* const* d_in, const int* in_sizes, int n_in,
                              void* d_out, int out_size) {
    const float* gx = (const float*)d_in[0];
    const float* gy = (const float*)d_in[1];
    const float* eps = (const float*)d_in[2];
    int N = in_sizes[0] / DDIM;
    int M = in_sizes[1] / DDIM;
    int L = in_sizes[2];
    if (N > NMAX || M > NMAX || N != M) return;
    int nn = N;

    float *Cxy, *Cxx, *Cyy, *sq, *vec;
    float2* Pbase;
    cudaGetSymbolAddress((void**)&Cxy, d_Cxy);
    cudaGetSymbolAddress((void**)&Cxx, d_Cxx);
    cudaGetSymbolAddress((void**)&Cyy, d_Cyy);
    cudaGetSymbolAddress((void**)&sq, d_sq);
    cudaGetSymbolAddress((void**)&vec, d_vec);
    cudaGetSymbolAddress((void**)&Pbase, d_P);
    float* sqx = sq;
    float* sqy = sq + NMAX;
    float2* P0 = Pbase;
    float2* P1 = Pbase + (size_t)PW * NMAX;
    float2* P2 = Pbase + 2 * (size_t)PW * NMAX;
#define V(i) (vec + (size_t)(i) * NMAX)

    float alog = -logf((float)N);
    float blog = -logf((float)M);

    sqnorm_kernel<<<(N + 7) / 8, 256>>>(gx, sqx, N, DDIM);
    sqnorm_kernel<<<(M + 7) / 8, 256>>>(gy, sqy, M, DDIM);
    cost_gemm_kernel<<<dim3(M / BM, N / BM), 256>>>(gx, gy, sqx, sqy, Cxy, M, DDIM, 0);
    cost_gemm_kernel<<<dim3(N / BM, N / BM), 256>>>(gx, gx, sqx, sqx, Cxx, N, DDIM, 1);
    cost_gemm_kernel<<<dim3(M / BM, M / BM), 256>>>(gy, gy, sqy, sqy, Cyy, M, DDIM, 1);

    int nbands = nn / 64;
    int cpr = nn / 1024;
    int blocksXY = nbands * cpr;
    int S = 0;
    for (int b = 0; b < nbands; b++) S += (nbands - b + 15) >> 4;
    int totalBlocks = blocksXY + 2 * S;

    StripP sp;
    sp.C[0] = Cxy; sp.C[1] = Cxx; sp.C[2] = Cyy;
    sp.P[0] = P0;  sp.P[1] = P1;  sp.P[2] = P2;
    sp.lwr[0] = alog; sp.lwc[0] = blog;
    sp.lwr[1] = alog; sp.lwc[1] = alog;
    sp.lwr[2] = blog; sp.lwc[2] = blog;
    sp.eps_list = eps;
    sp.nn = nn; sp.nbands = nbands; sp.cpr = cpr;
    sp.blocksXY = blocksXY; sp.blocksSym = S;

    S2J jb;
    jb.P[0] = P0; jb.colLim[0] = 0;      jb.chLim[0] = cpr;
    jb.P[1] = P0; jb.colLim[1] = nbands; jb.chLim[1] = 0;
    jb.P[2] = P1; jb.colLim[2] = -1;     jb.chLim[2] = -1;
    jb.P[3] = P2; jb.colLim[3] = -1;     jb.chLim[3] = -1;

    dim3 s2g(nn / 256, 4);

    // init
    sp.eps_idx = 0;
    sp.potr[0] = nullptr; sp.potc[0] = nullptr;
    sp.potr[1] = nullptr; sp.potc[1] = nullptr;
    sp.potr[2] = nullptr; sp.potc[2] = nullptr;
    strip_kernel<<<totalBlocks, 256>>>(sp);
    jb.oldv[0] = nullptr; jb.out[0] = V(3);
    jb.oldv[1] = nullptr; jb.out[1] = V(2);
    jb.oldv[2] = nullptr; jb.out[2] = V(0);
    jb.oldv[3] = nullptr; jb.out[3] = V(1);
    stage2_kernel<<<s2g, 256>>>(jb, eps, 0, nn, nbands);

    // iterations
    int cur = 0;
    for (int k = 0; k < L; k++) {
        int oth = cur ^ 4;
        sp.eps_idx = k;
        sp.potr[0] = V(cur + 3); sp.potc[0] = V(cur + 2);
        sp.potr[1] = V(cur + 0); sp.potc[1] = V(cur + 0);
        sp.potr[2] = V(cur + 1); sp.potc[2] = V(cur + 1);
        strip_kernel<<<totalBlocks, 256>>>(sp);
        jb.oldv[0] = V(cur + 3); jb.out[0] = V(oth + 3);
        jb.oldv[1] = V(cur + 2); jb.out[1] = V(oth + 2);
        jb.oldv[2] = V(cur + 0); jb.out[2] = V(oth + 0);
        jb.oldv[3] = V(cur + 1); jb.out[3] = V(oth + 1);
        stage2_kernel<<<s2g, 256>>>(jb, eps, k, nn, nbands);
        cur = oth;
    }

    // final extrapolation
    sp.eps_idx = L - 1;
    sp.potr[0] = V(cur + 3); sp.potc[0] = V(cur + 2);
    sp.potr[1] = V(cur + 0); sp.potc[1] = V(cur + 0);
    sp.potr[2] = V(cur + 1); sp.potc[2] = V(cur + 1);
    strip_kernel<<<totalBlocks, 256>>>(sp);
    jb.oldv[0] = nullptr; jb.out[0] = V(8);
    jb.oldv[1] = nullptr; jb.out[1] = V(9);
    jb.oldv[2] = nullptr; jb.out[2] = V(10);
    jb.oldv[3] = nullptr; jb.out[3] = V(11);
    stage2_kernel<<<s2g, 256>>>(jb, eps, L - 1, nn, nbands);

    final_reduce_kernel<<<1, 256>>>((float*)d_out, N);
#undef V
}

// round 17
// speedup vs baseline: 1.1989x; 1.1989x over previous
#include <cuda_runtime.h>
#include <math.h>
#include <stdint.h>

// ============================================================================
// Sinkhorn divergence, N=M=8192, D=64.
// Round 9: R7 strip kernel (best) + warp-parallel stage2 + streaming loads.
//  - strip: 64-row x 1024-col chunks, reg double-buffer prefetch, one
//    sync per 128-col panel, EX2 inline PTX, warp-uniform skip votes,
//    __ldcs (evict-first) on cost-matrix reads.
//  - stage2: warp per row; partial slots strided over lanes + shfl reduce
//    (was 128 serial dependent merge steps per thread).
// ============================================================================

#define NMAX  8192
#define DDIM  64
#define LOG2E 1.4426950408889634f
#define LN2   0.6931471805599453f
#define PW    136   // partial slots: 128 col-bands + 8 row-chunks

static __device__ float d_Cxy[(size_t)NMAX * NMAX];
static __device__ float d_Cxx[(size_t)NMAX * NMAX];   // upper tiles only
static __device__ float d_Cyy[(size_t)NMAX * NMAX];   // upper tiles only
static __device__ float d_sq[2][NMAX];
static __device__ float d_vec[12][NMAX];
static __device__ float2 d_P[3][(size_t)PW * NMAX];

__device__ __forceinline__ float ex2f(float x) {
    float y;
    asm("ex2.approx.ftz.f32 %0, %1;" : "=f"(y) : "f"(x));
    return y;
}
__device__ __forceinline__ float lg2f(float x) {
    float y;
    asm("lg2.approx.ftz.f32 %0, %1;" : "=f"(y) : "f"(x));
    return y;
}

// ---------------------------------------------------------------------------
__global__ void sqnorm_kernel(const float* __restrict__ X, float* __restrict__ out,
                              int n, int d) {
    int row = blockIdx.x * (blockDim.x >> 5) + (threadIdx.x >> 5);
    int lane = threadIdx.x & 31;
    if (row >= n) return;
    float s = 0.f;
    for (int c = lane; c < d; c += 32) {
        float v = X[(size_t)row * d + c];
        s += v * v;
    }
#pragma unroll
    for (int o = 16; o; o >>= 1) s += __shfl_xor_sync(0xFFFFFFFFu, s, o);
    if (lane == 0) out[row] = s;
}

// ---------------------------------------------------------------------------
#define BM 128
#define BKC 32

__global__ __launch_bounds__(256) void cost_gemm_kernel(
    const float* __restrict__ A, const float* __restrict__ B,
    const float* __restrict__ sqa, const float* __restrict__ sqb,
    float* __restrict__ C1, int nB, int d, int sym)
{
    int bj = blockIdx.x, bi = blockIdx.y;
    if (sym && bi > bj) return;

    __shared__ float As[BKC][BM + 4];
    __shared__ float Bs[BKC][BM + 4];

    int tid = threadIdx.x;
    int ti = tid & 15, tj = tid >> 4;
    int i0 = ti * 8, j0 = tj * 8;

    const float* Ab = A + (size_t)bi * BM * d;
    const float* Bb = B + (size_t)bj * BM * d;

    float acc[8][8];
#pragma unroll
    for (int a = 0; a < 8; a++)
#pragma unroll
        for (int b = 0; b < 8; b++) acc[a][b] = 0.f;

    for (int kk = 0; kk < d; kk += BKC) {
#pragma unroll
        for (int v = tid; v < 1024; v += 256) {
            int r = v >> 3, c4 = (v & 7) * 4;
            float4 a = *(const float4*)(Ab + (size_t)r * d + kk + c4);
            As[c4 + 0][r] = a.x; As[c4 + 1][r] = a.y;
            As[c4 + 2][r] = a.z; As[c4 + 3][r] = a.w;
            float4 b = *(const float4*)(Bb + (size_t)r * d + kk + c4);
            Bs[c4 + 0][r] = b.x; Bs[c4 + 1][r] = b.y;
            Bs[c4 + 2][r] = b.z; Bs[c4 + 3][r] = b.w;
        }
        __syncthreads();
#pragma unroll
        for (int k = 0; k < BKC; k++) {
            float4 a0 = *(const float4*)&As[k][i0];
            float4 a1 = *(const float4*)&As[k][i0 + 4];
            float4 b0 = *(const float4*)&Bs[k][j0];
            float4 b1 = *(const float4*)&Bs[k][j0 + 4];
            float av[8] = {a0.x, a0.y, a0.z, a0.w, a1.x, a1.y, a1.z, a1.w};
            float bv[8] = {b0.x, b0.y, b0.z, b0.w, b1.x, b1.y, b1.z, b1.w};
#pragma unroll
            for (int ii = 0; ii < 8; ii++)
#pragma unroll
                for (int jj = 0; jj < 8; jj++)
                    acc[ii][jj] += av[ii] * bv[jj];
        }
        __syncthreads();
    }

    float si[8], sj[8];
#pragma unroll
    for (int ii = 0; ii < 8; ii++) si[ii] = 0.5f * sqa[bi * BM + i0 + ii];
#pragma unroll
    for (int jj = 0; jj < 8; jj++) sj[jj] = 0.5f * sqb[bj * BM + j0 + jj];

#pragma unroll
    for (int ii = 0; ii < 8; ii++) {
        size_t off = (size_t)(bi * BM + i0 + ii) * nB + bj * BM + j0;
        float4 w0 = make_float4(
            fmaxf(si[ii] + sj[0] - acc[ii][0], 0.f),
            fmaxf(si[ii] + sj[1] - acc[ii][1], 0.f),
            fmaxf(si[ii] + sj[2] - acc[ii][2], 0.f),
            fmaxf(si[ii] + sj[3] - acc[ii][3], 0.f));
        float4 w1 = make_float4(
            fmaxf(si[ii] + sj[4] - acc[ii][4], 0.f),
            fmaxf(si[ii] + sj[5] - acc[ii][5], 0.f),
            fmaxf(si[ii] + sj[6] - acc[ii][6], 0.f),
            fmaxf(si[ii] + sj[7] - acc[ii][7], 0.f));
        *(float4*)(C1 + off) = w0;
        *(float4*)(C1 + off + 4) = w1;
    }
}

// ---------------------------------------------------------------------------
// strip kernel (R7 structure, software pipelined, __ldcs loads)
// ---------------------------------------------------------------------------
struct StripP {
    const float* C[3];
    float2*      P[3];
    const float* potr[3];
    const float* potc[3];
    float        lwr[3], lwc[3];
    const float* eps_list;
    int eps_idx;
    int nn, nbands, cpr, blocksXY, blocksSym;
};

__global__ __launch_bounds__(256, 2) void strip_kernel(StripP prm)
{
    int nn = prm.nn;
    int id = blockIdx.x;
    int mat, band, chunk;
    if (id < prm.blocksXY) {
        mat = 0;
        band = id / prm.cpr;
        chunk = id - band * prm.cpr;
    } else {
        id -= prm.blocksXY;
        mat = 1 + id / prm.blocksSym;
        int sid = id - (mat - 1) * prm.blocksSym;
        int b = 0;
        for (;;) {
            int nc = (prm.nbands - b + 15) >> 4;
            if (sid < nc) break;
            sid -= nc; b++;
        }
        band = b; chunk = sid;
    }
    int c0, c1;
    if (mat == 0) { c0 = chunk << 10; c1 = c0 + 1024; }
    else { c0 = (band << 6) + (chunk << 10); c1 = min(c0 + 1024, nn); }
    int row0 = band << 6;

    const float* __restrict__ C = prm.C[mat];
    float2* __restrict__ P = prm.P[mat];
    const float* potr = prm.potr[mat];
    const float* potc = prm.potc[mat];

    float eps = prm.eps_list[prm.eps_idx];
    float ie2 = LOG2E / eps;
    float lwr2 = prm.lwr[mat] * LOG2E;
    float lwc2 = prm.lwc[mat] * LOG2E;

    int w = threadIdx.x >> 5, l = threadIdx.x & 31;
    int rbase = row0 + w * 8;

    float har[8];
#pragma unroll
    for (int r = 0; r < 8; r++)
        har[r] = potr ? fmaf(potr[rbase + r], ie2, lwr2) : lwr2;

    float rmx[8], rs[8];
#pragma unroll
    for (int r = 0; r < 8; r++) { rmx[r] = -3.4e38f; rs[r] = 0.f; }

    __shared__ float2 smc[2][8][128];
    const float* Cb = C + (size_t)rbase * nn;

#define LOADP(U, H, PP) do {                                                   \
        int _j = (PP) + l * 4;                                                 \
        _Pragma("unroll")                                                      \
        for (int _r = 0; _r < 8; _r++)                                         \
            U[_r] = __ldcs((const float4*)(Cb + (size_t)_r * nn + _j));        \
        if (potc) {                                                            \
            float4 _p = *(const float4*)(potc + _j);                           \
            H.x = fmaf(_p.x, ie2, lwc2); H.y = fmaf(_p.y, ie2, lwc2);          \
            H.z = fmaf(_p.z, ie2, lwc2); H.w = fmaf(_p.w, ie2, lwc2);          \
        } else H = make_float4(lwc2, lwc2, lwc2, lwc2);                        \
    } while (0)

#define PROCESS(U, H, PP, PAR) do {                                            \
        float cm0 = -3.4e38f, cm1 = -3.4e38f, cm2 = -3.4e38f, cm3 = -3.4e38f;  \
        _Pragma("unroll")                                                      \
        for (int r = 0; r < 8; r++) {                                          \
            U[r].x *= -ie2; U[r].y *= -ie2; U[r].z *= -ie2; U[r].w *= -ie2;    \
            float v0 = U[r].x + H.x, v1 = U[r].y + H.y;                        \
            float v2 = U[r].z + H.z, v3 = U[r].w + H.w;                        \
            float m4 = fmaxf(fmaxf(v0, v1), fmaxf(v2, v3));                    \
            if (__any_sync(0xFFFFFFFFu, m4 > rmx[r] - 24.f)) {                 \
                float mn = fmaxf(rmx[r], m4);                                  \
                float e = ex2f(v0 - mn) + ex2f(v1 - mn)                        \
                        + ex2f(v2 - mn) + ex2f(v3 - mn);                       \
                rs[r] = fmaf(rs[r], ex2f(rmx[r] - mn), e);                     \
                rmx[r] = mn;                                                   \
            }                                                                  \
            float a = har[r];                                                  \
            cm0 = fmaxf(cm0, U[r].x + a); cm1 = fmaxf(cm1, U[r].y + a);        \
            cm2 = fmaxf(cm2, U[r].z + a); cm3 = fmaxf(cm3, U[r].w + a);        \
        }                                                                      \
        float cs0 = 0.f, cs1 = 0.f, cs2 = 0.f, cs3 = 0.f;                      \
        _Pragma("unroll")                                                      \
        for (int r = 0; r < 8; r++) {                                          \
            float t0 = har[r] - cm0, t1 = har[r] - cm1;                        \
            float t2 = har[r] - cm2, t3 = har[r] - cm3;                        \
            float w0 = U[r].x + t0, w1 = U[r].y + t1;                          \
            float w2 = U[r].z + t2, w3 = U[r].w + t3;                          \
            float m4c = fmaxf(fmaxf(w0, w1), fmaxf(w2, w3));                   \
            if (__any_sync(0xFFFFFFFFu, m4c > -24.f)) {                        \
                cs0 += ex2f(w0); cs1 += ex2f(w1);                              \
                cs2 += ex2f(w2); cs3 += ex2f(w3);                              \
            }                                                                  \
        }                                                                      \
        smc[PAR][w][l * 4 + 0] = make_float2(cm0, cs0);                       \
        smc[PAR][w][l * 4 + 1] = make_float2(cm1, cs1);                       \
        smc[PAR][w][l * 4 + 2] = make_float2(cm2, cs2);                       \
        smc[PAR][w][l * 4 + 3] = make_float2(cm3, cs3);                       \
        __syncthreads();                                                       \
        if (threadIdx.x < 128) {                                               \
            int cc = threadIdx.x;                                              \
            float2 a = smc[PAR][0][cc];                                        \
            float m = a.x, s = a.y;                                            \
            _Pragma("unroll")                                                  \
            for (int ww = 1; ww < 8; ww++) {                                   \
                float2 b = smc[PAR][ww][cc];                                   \
                float mn = fmaxf(m, b.x);                                      \
                s = fmaf(s, ex2f(m - mn), b.y * ex2f(b.x - mn));               \
                m = mn;                                                        \
            }                                                                  \
            int jj = (PP) + cc;                                                \
            if (!(mat && ((jj >> 6) == band)))                                 \
                P[(size_t)band * nn + jj] = make_float2(m, s);                 \
        }                                                                      \
    } while (0)

    float4 u[8], un[8], hcur, hn;
    int p = c0, par = 0;
    if (p + 128 <= c1) LOADP(u, hcur, p);
    while (p + 128 <= c1) {
        int pn = p + 128;
        if (pn + 128 <= c1) LOADP(un, hn, pn);
        PROCESS(u, hcur, p, par);
#pragma unroll
        for (int r = 0; r < 8; r++) u[r] = un[r];
        hcur = hn;
        par ^= 1;
        p = pn;
    }

    // ---- 64-col tail panel ----
    if (p < c1) {
        int j = p + l * 2;
        float2 u2[8];
#pragma unroll
        for (int r = 0; r < 8; r++)
            u2[r] = __ldcs((const float2*)(Cb + (size_t)r * nn + j));
        float h0 = lwc2, h1 = lwc2;
        if (potc) {
            h0 = fmaf(potc[j], ie2, lwc2);
            h1 = fmaf(potc[j + 1], ie2, lwc2);
        }
        float cm0 = -3.4e38f, cm1 = -3.4e38f;
#pragma unroll
        for (int r = 0; r < 8; r++) {
            u2[r].x *= -ie2; u2[r].y *= -ie2;
            float v0 = u2[r].x + h0, v1 = u2[r].y + h1;
            float m2v = fmaxf(v0, v1);
            if (__any_sync(0xFFFFFFFFu, m2v > rmx[r] - 24.f)) {
                float mn = fmaxf(rmx[r], m2v);
                float e = ex2f(v0 - mn) + ex2f(v1 - mn);
                rs[r] = fmaf(rs[r], ex2f(rmx[r] - mn), e);
                rmx[r] = mn;
            }
            float a = har[r];
            cm0 = fmaxf(cm0, u2[r].x + a);
            cm1 = fmaxf(cm1, u2[r].y + a);
        }
        float cs0 = 0.f, cs1 = 0.f;
#pragma unroll
        for (int r = 0; r < 8; r++) {
            float a = har[r];
            float w0 = u2[r].x + a - cm0, w1 = u2[r].y + a - cm1;
            float m2c = fmaxf(w0, w1);
            if (__any_sync(0xFFFFFFFFu, m2c > -24.f)) {
                cs0 += ex2f(w0); cs1 += ex2f(w1);
            }
        }
        smc[par][w][l * 2 + 0] = make_float2(cm0, cs0);
        smc[par][w][l * 2 + 1] = make_float2(cm1, cs1);
        __syncthreads();
        if (threadIdx.x < 64) {
            int cc = threadIdx.x;
            float2 a = smc[par][0][cc];
            float m = a.x, s = a.y;
#pragma unroll
            for (int ww = 1; ww < 8; ww++) {
                float2 b = smc[par][ww][cc];
                float mn = fmaxf(m, b.x);
                s = fmaf(s, ex2f(m - mn), b.y * ex2f(b.x - mn));
                m = mn;
            }
            int jj = p + cc;
            if (!(mat && ((jj >> 6) == band)))
                P[(size_t)band * nn + jj] = make_float2(m, s);
        }
        __syncthreads();
    }

    // ---- row partial output ----
#pragma unroll
    for (int r = 0; r < 8; r++) {
        float m = rmx[r], s = rs[r];
#pragma unroll
        for (int o = 16; o; o >>= 1) {
            float m2 = __shfl_xor_sync(0xFFFFFFFFu, m, o);
            float s2 = __shfl_xor_sync(0xFFFFFFFFu, s, o);
            float mn = fmaxf(m, m2);
            s = fmaf(s, ex2f(m - mn), s2 * ex2f(m2 - mn));
            m = mn;
        }
        if (l == 0)
            P[(size_t)(prm.nbands + chunk) * nn + rbase + r] = make_float2(m, s);
    }
#undef LOADP
#undef PROCESS
}

// ---------------------------------------------------------------------------
// stage 2: WARP per row; slots strided across lanes then shfl-reduced.
// ---------------------------------------------------------------------------
struct S2J {
    const float2* P[4];
    const float*  oldv[4];
    float*        out[4];
    int colLim[4];
    int chLim[4];
};

__global__ __launch_bounds__(256) void stage2_kernel(
    S2J jb, const float* __restrict__ eps_list, int eps_idx, int nn, int nbands)
{
    int job = blockIdx.y;
    int row = blockIdx.x * 8 + (threadIdx.x >> 5);
    int l = threadIdx.x & 31;
    float eps = eps_list[eps_idx];
    const float2* __restrict__ P = jb.P[job];
    int band = row >> 6;
    int cl = jb.colLim[job]; if (cl < 0) cl = band;
    int ch = jb.chLim[job];  if (ch < 0) ch = (nbands - band + 15) >> 4;

    float mx = -3.4e38f, s = 0.f;
    for (int t = l; t < cl; t += 32) {
        float2 p = P[(size_t)t * nn + row];
        float mn = fmaxf(mx, p.x);
        s = fmaf(s, ex2f(mx - mn), p.y * ex2f(p.x - mn));
        mx = mn;
    }
    for (int t = l; t < ch; t += 32) {
        float2 p = P[(size_t)(nbands + t) * nn + row];
        float mn = fmaxf(mx, p.x);
        s = fmaf(s, ex2f(mx - mn), p.y * ex2f(p.x - mn));
        mx = mn;
    }
#pragma unroll
    for (int o = 16; o; o >>= 1) {
        float m2 = __shfl_xor_sync(0xFFFFFFFFu, mx, o);
        float s2 = __shfl_xor_sync(0xFFFFFFFFu, s, o);
        float mn = fmaxf(mx, m2);
        s = fmaf(s, ex2f(mx - mn), s2 * ex2f(m2 - mn));
        mx = mn;
    }
    if (l == 0) {
        float res = -eps * LN2 * (mx + lg2f(s));
        const float* ov = jb.oldv[job];
        jb.out[job][row] = ov ? 0.5f * (ov[row] + res) : res;
    }
}

// ---------------------------------------------------------------------------
__global__ void final_reduce_kernel(float* __restrict__ out, int n) {
    __shared__ float red[256];
    float s = 0.f;
    for (int i = threadIdx.x; i < n; i += 256)
        s += (d_vec[8][i] - d_vec[10][i]) + (d_vec[9][i] - d_vec[11][i]);
    red[threadIdx.x] = s;
    __syncthreads();
    for (int o = 128; o; o >>= 1) {
        if (threadIdx.x < o) red[threadIdx.x] += red[threadIdx.x + o];
        __syncthreads();
    }
    if (threadIdx.x == 0) out[0] = red[0] / (float)n;
}

// ---------------------------------------------------------------------------
extern "C" void kernel_launch(void* const* d_in, const int* in_sizes, int n_in,
                              void* d_out, int out_size) {
    const float* gx = (const float*)d_in[0];
    const float* gy = (const float*)d_in[1];
    const float* eps = (const float*)d_in[2];
    int N = in_sizes[0] / DDIM;
    int M = in_sizes[1] / DDIM;
    int L = in_sizes[2];
    if (N > NMAX || M > NMAX || N != M) return;
    int nn = N;

    float *Cxy, *Cxx, *Cyy, *sq, *vec;
    float2* Pbase;
    cudaGetSymbolAddress((void**)&Cxy, d_Cxy);
    cudaGetSymbolAddress((void**)&Cxx, d_Cxx);
    cudaGetSymbolAddress((void**)&Cyy, d_Cyy);
    cudaGetSymbolAddress((void**)&sq, d_sq);
    cudaGetSymbolAddress((void**)&vec, d_vec);
    cudaGetSymbolAddress((void**)&Pbase, d_P);
    float* sqx = sq;
    float* sqy = sq + NMAX;
    float2* P0 = Pbase;
    float2* P1 = Pbase + (size_t)PW * NMAX;
    float2* P2 = Pbase + 2 * (size_t)PW * NMAX;
#define V(i) (vec + (size_t)(i) * NMAX)

    float alog = -logf((float)N);
    float blog = -logf((float)M);

    sqnorm_kernel<<<(N + 7) / 8, 256>>>(gx, sqx, N, DDIM);
    sqnorm_kernel<<<(M + 7) / 8, 256>>>(gy, sqy, M, DDIM);
    cost_gemm_kernel<<<dim3(M / BM, N / BM), 256>>>(gx, gy, sqx, sqy, Cxy, M, DDIM, 0);
    cost_gemm_kernel<<<dim3(N / BM, N / BM), 256>>>(gx, gx, sqx, sqx, Cxx, N, DDIM, 1);
    cost_gemm_kernel<<<dim3(M / BM, M / BM), 256>>>(gy, gy, sqy, sqy, Cyy, M, DDIM, 1);

    int nbands = nn / 64;
    int cpr = nn / 1024;
    int blocksXY = nbands * cpr;
    int S = 0;
    for (int b = 0; b < nbands; b++) S += (nbands - b + 15) >> 4;
    int totalBlocks = blocksXY + 2 * S;

    StripP sp;
    sp.C[0] = Cxy; sp.C[1] = Cxx; sp.C[2] = Cyy;
    sp.P[0] = P0;  sp.P[1] = P1;  sp.P[2] = P2;
    sp.lwr[0] = alog; sp.lwc[0] = blog;
    sp.lwr[1] = alog; sp.lwc[1] = alog;
    sp.lwr[2] = blog; sp.lwc[2] = blog;
    sp.eps_list = eps;
    sp.nn = nn; sp.nbands = nbands; sp.cpr = cpr;
    sp.blocksXY = blocksXY; sp.blocksSym = S;

    S2J jb;
    jb.P[0] = P0; jb.colLim[0] = 0;      jb.chLim[0] = cpr;
    jb.P[1] = P0; jb.colLim[1] = nbands; jb.chLim[1] = 0;
    jb.P[2] = P1; jb.colLim[2] = -1;     jb.chLim[2] = -1;
    jb.P[3] = P2; jb.colLim[3] = -1;     jb.chLim[3] = -1;

    dim3 s2g(nn / 8, 4);

    // init
    sp.eps_idx = 0;
    sp.potr[0] = nullptr; sp.potc[0] = nullptr;
    sp.potr[1] = nullptr; sp.potc[1] = nullptr;
    sp.potr[2] = nullptr; sp.potc[2] = nullptr;
    strip_kernel<<<totalBlocks, 256>>>(sp);
    jb.oldv[0] = nullptr; jb.out[0] = V(3);
    jb.oldv[1] = nullptr; jb.out[1] = V(2);
    jb.oldv[2] = nullptr; jb.out[2] = V(0);
    jb.oldv[3] = nullptr; jb.out[3] = V(1);
    stage2_kernel<<<s2g, 256>>>(jb, eps, 0, nn, nbands);

    // iterations
    int cur = 0;
    for (int k = 0; k < L; k++) {
        int oth = cur ^ 4;
        sp.eps_idx = k;
        sp.potr[0] = V(cur + 3); sp.potc[0] = V(cur + 2);
        sp.potr[1] = V(cur + 0); sp.potc[1] = V(cur + 0);
        sp.potr[2] = V(cur + 1); sp.potc[2] = V(cur + 1);
        strip_kernel<<<totalBlocks, 256>>>(sp);
        jb.oldv[0] = V(cur + 3); jb.out[0] = V(oth + 3);
        jb.oldv[1] = V(cur + 2); jb.out[1] = V(oth + 2);
        jb.oldv[2] = V(cur + 0); jb.out[2] = V(oth + 0);
        jb.oldv[3] = V(cur + 1); jb.out[3] = V(oth + 1);
        stage2_kernel<<<s2g, 256>>>(jb, eps, k, nn, nbands);
        cur = oth;
    }

    // final extrapolation
    sp.eps_idx = L - 1;
    sp.potr[0] = V(cur + 3); sp.potc[0] = V(cur + 2);
    sp.potr[1] = V(cur + 0); sp.potc[1] = V(cur + 0);
    sp.potr[2] = V(cur + 1); sp.potc[2] = V(cur + 1);
    strip_kernel<<<totalBlocks, 256>>>(sp);
    jb.oldv[0] = nullptr; jb.out[0] = V(8);
    jb.oldv[1] = nullptr; jb.out[1] = V(9);
    jb.oldv[2] = nullptr; jb.out[2] = V(10);
    jb.oldv[3] = nullptr; jb.out[3] = V(11);
    stage2_kernel<<<s2g, 256>>>(jb, eps, L - 1, nn, nbands);

    final_reduce_kernel<<<1, 256>>>((float*)d_out, N);
#undef V
}